// round 16
// baseline (speedup 1.0000x reference)
#include <cuda_runtime.h>
#include <cuda_fp16.h>
#include <math.h>
#include <stdint.h>

// Problem constants
#define EMB   1024
#define NROWS 4096          // B * S
#define NH    16
#define HD    64
#define SEQ   1024
#define NB    4
#define NEGV  (-1e9f)

// Scratch (device globals: allocation-free, graph-capturable)
__device__ float          g_P [2][(size_t)NROWS * EMB];      // proj outputs (pre-LN)
__device__ __half         g_x  [(size_t)NROWS * EMB];        // x, fp16
__device__ __half         g_w  [2][(size_t)EMB * EMB];       // W^T fp16
__device__ __half         g_q  [(size_t)NROWS * EMB];        // Q fp16
__device__ __half         g_k  [(size_t)NROWS * EMB];        // K fp16
__device__ float          g_S  [(size_t)NB * NH * SEQ * SEQ]; // scores, 256 MB
__device__ unsigned char  g_M  [(size_t)NB * SEQ * SEQ];     // symmetric mask, 4 MB

// ===========================================================================
// helpers
// ===========================================================================
__device__ __forceinline__ uint32_t smem_u32(const void* p) {
    uint32_t a;
    asm("{ .reg .u64 t; cvta.to.shared.u64 t, %1; cvt.u32.u64 %0, t; }"
        : "=r"(a) : "l"(p));
    return a;
}

#define CP16(s, g) \
    asm volatile("cp.async.cg.shared.global [%0], [%1], 16;" :: "r"(s), "l"(g))
#define CP_COMMIT() asm volatile("cp.async.commit_group;" ::: "memory")
#define CP_WAIT(n)  asm volatile("cp.async.wait_group %0;" :: "n"(n) : "memory")

__device__ __forceinline__ void ldsm4(uint32_t addr, uint32_t r[4]) {
    asm volatile("ldmatrix.sync.aligned.m8n8.x4.shared.b16 {%0,%1,%2,%3}, [%4];"
        : "=r"(r[0]), "=r"(r[1]), "=r"(r[2]), "=r"(r[3]) : "r"(addr));
}
__device__ __forceinline__ void mma16816(float c[4], const uint32_t a[4],
                                         uint32_t b0, uint32_t b1) {
    asm volatile(
        "mma.sync.aligned.m16n8k16.row.col.f32.f16.f16.f32 "
        "{%0,%1,%2,%3}, {%4,%5,%6,%7}, {%8,%9}, {%0,%1,%2,%3};"
        : "+f"(c[0]), "+f"(c[1]), "+f"(c[2]), "+f"(c[3])
        : "r"(a[0]), "r"(a[1]), "r"(a[2]), "r"(a[3]), "r"(b0), "r"(b1));
}

// ===========================================================================
// core 128x128 GEMM tile, C = A @ B^T, fp16 operands, fp32 accumulate.
// ===========================================================================
template <int KCHUNKS>
__device__ __forceinline__ void gemm_tile(
    const __half* __restrict__ A,
    const __half* __restrict__ B,
    float acc[2][8][4])
{
    __shared__ __half sm[2][2][128 * 40];
    const uint32_t sbase = smem_u32(&sm[0][0][0]);
    const int t = threadIdx.x, lane = t & 31, wid = t >> 5;
    const int wm = wid & 3, wn = wid >> 2;

    const int rA0 = t >> 2, cc = t & 3;
    const int rA1 = rA0 + 64;
    const uint32_t so0 = (uint32_t)(rA0 * 80 + cc * 16);
    const uint32_t so1 = (uint32_t)(rA1 * 80 + cc * 16);

    uint32_t aoff[2], boff[4];
#pragma unroll
    for (int mf = 0; mf < 2; mf++)
        aoff[mf] = (uint32_t)((wm * 32 + mf * 16 + (lane & 15)) * 80 + (lane >> 4) * 16);
#pragma unroll
    for (int g = 0; g < 4; g++)
        boff[g] = (uint32_t)((wn * 64 + g * 16 + (lane & 15)) * 80 + (lane >> 4) * 16);

    auto issue = [&](int buf, int c) {
        const uint32_t sA = sbase + (uint32_t)buf * 20480u;
        const uint32_t sB = sA + 10240u;
        const __half* ga = A + c * 32;
        const __half* gb = B + c * 32;
        CP16(sA + so0, ga + (size_t)rA0 * EMB + cc * 8);
        CP16(sA + so1, ga + (size_t)rA1 * EMB + cc * 8);
        CP16(sB + so0, gb + (size_t)rA0 * EMB + cc * 8);
        CP16(sB + so1, gb + (size_t)rA1 * EMB + cc * 8);
        CP_COMMIT();
    };

    issue(0, 0);
    for (int c = 0; c < KCHUNKS; c++) {
        const int buf = c & 1;
        if (c + 1 < KCHUNKS) { issue(buf ^ 1, c + 1); CP_WAIT(1); }
        else                 { CP_WAIT(0); }
        __syncthreads();
        const uint32_t sA = sbase + (uint32_t)buf * 20480u;
        const uint32_t sB = sA + 10240u;
#pragma unroll
        for (int ks = 0; ks < 2; ks++) {
            uint32_t a0[4], a1[4], b0[4], b1[4], b2[4], b3[4];
            ldsm4(sA + aoff[0] + ks * 32, a0);
            ldsm4(sA + aoff[1] + ks * 32, a1);
            ldsm4(sB + boff[0] + ks * 32, b0);
            ldsm4(sB + boff[1] + ks * 32, b1);
            ldsm4(sB + boff[2] + ks * 32, b2);
            ldsm4(sB + boff[3] + ks * 32, b3);
            mma16816(acc[0][0], a0, b0[0], b0[2]);
            mma16816(acc[0][1], a0, b0[1], b0[3]);
            mma16816(acc[1][0], a1, b0[0], b0[2]);
            mma16816(acc[1][1], a1, b0[1], b0[3]);
            mma16816(acc[0][2], a0, b1[0], b1[2]);
            mma16816(acc[0][3], a0, b1[1], b1[3]);
            mma16816(acc[1][2], a1, b1[0], b1[2]);
            mma16816(acc[1][3], a1, b1[1], b1[3]);
            mma16816(acc[0][4], a0, b2[0], b2[2]);
            mma16816(acc[0][5], a0, b2[1], b2[3]);
            mma16816(acc[1][4], a1, b2[0], b2[2]);
            mma16816(acc[1][5], a1, b2[1], b2[3]);
            mma16816(acc[0][6], a0, b3[0], b3[2]);
            mma16816(acc[0][7], a0, b3[1], b3[3]);
            mma16816(acc[1][6], a1, b3[0], b3[2]);
            mma16816(acc[1][7], a1, b3[1], b3[3]);
        }
        __syncthreads();
    }
}

// ===========================================================================
// Kernel A: x -> fp16
// ===========================================================================
__global__ __launch_bounds__(256) void split_x(const float* __restrict__ x)
{
    size_t i = ((size_t)blockIdx.x * 256 + threadIdx.x) * 4;
    float4 v = *(const float4*)(x + i);
    __half2 p0 = __floats2half2_rn(v.x, v.y);
    __half2 p1 = __floats2half2_rn(v.z, v.w);
    *(__half2*)(g_x + i)     = p0;
    *(__half2*)(g_x + i + 2) = p1;
}

// ===========================================================================
// Kernel B: transpose W -> W^T fp16.  grid (16,16,2), 64x64 tiles, 256 thr
// ===========================================================================
__global__ __launch_bounds__(256) void split_wt(
    const float* __restrict__ Wq, const float* __restrict__ Wk)
{
    __shared__ float t[64][65];
    const int which = blockIdx.z;
    const float* __restrict__ W = which ? Wk : Wq;
    const int n0 = blockIdx.x * 64, k0 = blockIdx.y * 64;
    const int c = threadIdx.x & 63, rb = threadIdx.x >> 6;

#pragma unroll
    for (int rr = 0; rr < 16; rr++) {
        int r = rb * 16 + rr;
        t[r][c] = W[(size_t)(k0 + r) * EMB + n0 + c];
    }
    __syncthreads();
#pragma unroll
    for (int rr = 0; rr < 16; rr++) {
        int r = rb * 16 + rr;
        float v = t[c][r];
        g_w[which][(size_t)(n0 + r) * EMB + (size_t)(k0 + c)] = __float2half_rn(v);
    }
}

// ===========================================================================
// Kernel B2: symmetric mask.  M[b][q][k] = mask[b][q][k] | mask[b][k][q]
// ===========================================================================
__global__ __launch_bounds__(256) void mask_or(const int* __restrict__ mask)
{
    __shared__ int tB[32][33];
    const int b  = blockIdx.z;
    const int q0 = blockIdx.y * 32;
    const int k0 = blockIdx.x * 32;
    const int r  = threadIdx.x >> 3;
    const int c4 = (threadIdx.x & 7) * 4;

    int4 tb = *(const int4*)&mask[((size_t)(b * SEQ + k0 + r)) * SEQ + q0 + c4];
    tB[r][c4 + 0] = tb.x; tB[r][c4 + 1] = tb.y;
    tB[r][c4 + 2] = tb.z; tB[r][c4 + 3] = tb.w;
    __syncthreads();

    int4 a = *(const int4*)&mask[((size_t)(b * SEQ + q0 + r)) * SEQ + k0 + c4];
    uchar4 o;
    o.x = (a.x | tB[c4 + 0][r]) ? 1 : 0;
    o.y = (a.y | tB[c4 + 1][r]) ? 1 : 0;
    o.z = (a.z | tB[c4 + 2][r]) ? 1 : 0;
    o.w = (a.w | tB[c4 + 3][r]) ? 1 : 0;
    *(uchar4*)&g_M[((size_t)(b * SEQ + q0 + r)) * SEQ + k0 + c4] = o;
}

// ===========================================================================
// Kernel C: projection GEMM, P = x @ W + b.  PERSISTENT: grid 296 CTAs
// (2/SM x 148), each strides over the 512 tiles -> balanced waves, no tail.
// tile t: which = t >> 8, m-tile = (t & 255) >> 3, n-tile = t & 7
// ===========================================================================
#define PROJ_TILES 512
__global__ __launch_bounds__(256, 2) void proj_mma(
    const float* __restrict__ bq, const float* __restrict__ bk)
{
    const int lane = threadIdx.x & 31, wid = threadIdx.x >> 5;
    const int wm = wid & 3, wn = wid >> 2;

    for (int tile = blockIdx.x; tile < PROJ_TILES; tile += gridDim.x) {
        const int which = tile >> 8;
        const int m0 = ((tile & 255) >> 3) * 128;
        const int n0 = (tile & 7) * 128;
        const __half* A = g_x + (size_t)m0 * EMB;
        const __half* B = g_w[which] + (size_t)n0 * EMB;

        float acc[2][8][4] = {};
        gemm_tile<32>(A, B, acc);

        const float* __restrict__ bias = which ? bk : bq;
        float* __restrict__ P = g_P[which];

#pragma unroll
        for (int mf = 0; mf < 2; mf++) {
#pragma unroll
            for (int j = 0; j < 8; j++) {
                int row = m0 + wm * 32 + mf * 16 + (lane >> 2);
                int col = n0 + wn * 64 + j * 8 + (lane & 3) * 2;
                float b0 = bias[col], b1 = bias[col + 1];
                float2 o0 = make_float2(acc[mf][j][0] + b0, acc[mf][j][1] + b1);
                float2 o1 = make_float2(acc[mf][j][2] + b0, acc[mf][j][3] + b1);
                *(float2*)&P[(size_t)row * EMB + col]       = o0;
                *(float2*)&P[(size_t)(row + 8) * EMB + col] = o1;
            }
        }
        __syncthreads();   // smem reuse across persistent iterations
    }
}

// ---------------------------------------------------------------------------
// fused pair block reduction (sum), 256 threads, 2 barriers
// ---------------------------------------------------------------------------
__device__ __forceinline__ float2 block_reduce_pair(float a, float b)
{
    __shared__ float red[8][2];
    const int lane = threadIdx.x & 31;
    const int w    = threadIdx.x >> 5;
#pragma unroll
    for (int o = 16; o; o >>= 1) {
        a += __shfl_xor_sync(0xffffffffu, a, o);
        b += __shfl_xor_sync(0xffffffffu, b, o);
    }
    if (lane == 0) { red[w][0] = a; red[w][1] = b; }
    __syncthreads();
    if (w == 0) {
        float x = (lane < 8) ? red[lane][0] : 0.f;
        float y = (lane < 8) ? red[lane][1] : 0.f;
#pragma unroll
        for (int o = 4; o; o >>= 1) {
            x += __shfl_xor_sync(0xffffffffu, x, o);
            y += __shfl_xor_sync(0xffffffffu, y, o);
        }
        if (lane == 0) { red[0][0] = x; red[0][1] = y; }
    }
    __syncthreads();
    return make_float2(red[0][0], red[0][1]);
}

// ---------------------------------------------------------------------------
// Kernel D: LayerNorm + ReLU -> fp16.  grid (4096, 2), 256 threads
// ---------------------------------------------------------------------------
__global__ __launch_bounds__(256) void ln_relu(
    const float* __restrict__ gq, const float* __restrict__ bqn,
    const float* __restrict__ gk, const float* __restrict__ bkn)
{
    const int row   = blockIdx.x;
    const int which = blockIdx.y;
    const int tid   = threadIdx.x;
    const float* __restrict__ gamma = which ? gk : gq;
    const float* __restrict__ beta  = which ? bkn : bqn;

    float4 v = ((const float4*)g_P[which])[(size_t)row * 256 + tid];
    float s  = v.x + v.y + v.z + v.w;
    float s2 = v.x * v.x + v.y * v.y + v.z * v.z + v.w * v.w;

    float2 SS = block_reduce_pair(s, s2);

    const float mu  = SS.x * (1.f / EMB);
    const float var = SS.y * (1.f / EMB) - mu * mu;
    const float rs  = rsqrtf(var + 1e-5f);

    const int c = tid * 4;
    float f[4];
    f[0] = fmaxf((v.x - mu) * rs * gamma[c + 0] + beta[c + 0], 0.f);
    f[1] = fmaxf((v.y - mu) * rs * gamma[c + 1] + beta[c + 1], 0.f);
    f[2] = fmaxf((v.z - mu) * rs * gamma[c + 2] + beta[c + 2], 0.f);
    f[3] = fmaxf((v.w - mu) * rs * gamma[c + 3] + beta[c + 3], 0.f);

    __half* dst = which ? g_k : g_q;
    size_t base = (size_t)row * EMB + c;
    *(__half2*)(dst + base)     = __floats2half2_rn(f[0], f[1]);
    *(__half2*)(dst + base + 2) = __floats2half2_rn(f[2], f[3]);
}

// ===========================================================================
// Kernel E: score GEMM. S[b,h][q][k] = (Q_h . K_h)/8.  grid (8 kt, 8 qt, 64 bh)
// ===========================================================================
__global__ __launch_bounds__(256, 2) void score_mma()
{
    const int kt = blockIdx.x, qt = blockIdx.y, bh = blockIdx.z;
    const int b = bh >> 4, h = bh & 15;

    const __half* A = g_q + (size_t)(b * SEQ + qt * 128) * EMB + h * HD;
    const __half* B = g_k + (size_t)(b * SEQ + kt * 128) * EMB + h * HD;

    float acc[2][8][4] = {};
    gemm_tile<2>(A, B, acc);

    const int lane = threadIdx.x & 31, wid = threadIdx.x >> 5;
    const int wm = wid & 3, wn = wid >> 2;

#pragma unroll
    for (int mf = 0; mf < 2; mf++) {
#pragma unroll
        for (int j = 0; j < 8; j++) {
            int q   = qt * 128 + wm * 32 + mf * 16 + (lane >> 2);
            int col = kt * 128 + wn * 64 + j * 8 + (lane & 3) * 2;
            float2 o0 = make_float2(acc[mf][j][0] * 0.125f, acc[mf][j][1] * 0.125f);
            float2 o1 = make_float2(acc[mf][j][2] * 0.125f, acc[mf][j][3] * 0.125f);
            float* S = g_S + ((size_t)bh * SEQ) * SEQ;
            *(float2*)&S[(size_t)q * SEQ + col]       = o0;
            *(float2*)&S[(size_t)(q + 8) * SEQ + col] = o1;
        }
    }
}

// ---------------------------------------------------------------------------
// Kernel F: no-max softmax + mean over heads, MLP-preserving schedule.
// ---------------------------------------------------------------------------
__global__ __launch_bounds__(256, 2) void softmax_mean(float* __restrict__ out)
{
    __shared__ float sred[16][8];
    __shared__ float gsumv[16];
    __shared__ float rinv[16];

    const int q    = blockIdx.x;
    const int b    = blockIdx.y;
    const int tid  = threadIdx.x;
    const int lane = tid & 31;
    const int wid  = tid >> 5;

    uchar4 mb = ((const uchar4*)(g_M + ((size_t)(b * SEQ + q)) * SEQ))[tid];
    const bool m0 = mb.x, m1 = mb.y, m2 = mb.z, m3 = mb.w;

    // phase 1: batched loads, cheap mask-select body
    float sc[16][4];
#pragma unroll
    for (int h = 0; h < NH; h++) {
        const float4* Sp = (const float4*)(g_S + (((size_t)(b * NH + h) * SEQ + q) << 10));
        float4 s = Sp[tid];
        sc[h][0] = m0 ? NEGV : s.x;
        sc[h][1] = m1 ? NEGV : s.y;
        sc[h][2] = m2 ? NEGV : s.z;
        sc[h][3] = m3 ? NEGV : s.w;
    }

    // phase 2: exp + per-thread partial sums
    float tval[16];
#pragma unroll
    for (int h = 0; h < NH; h++) {
        sc[h][0] = __expf(sc[h][0]);
        sc[h][1] = __expf(sc[h][1]);
        sc[h][2] = __expf(sc[h][2]);
        sc[h][3] = __expf(sc[h][3]);
        tval[h] = (sc[h][0] + sc[h][1]) + (sc[h][2] + sc[h][3]);
    }

    // single batched sum reduction for all 16 heads
#pragma unroll
    for (int h = 0; h < NH; h++) {
        float v = tval[h];
#pragma unroll
        for (int o = 16; o; o >>= 1) v += __shfl_xor_sync(0xffffffffu, v, o);
        if (lane == h) sred[h][wid] = v;
    }
    __syncthreads();
    if (tid < 128) {
        const int h = tid >> 3, j = tid & 7;
        float v = sred[h][j];
        v += __shfl_xor_sync(0xffffffffu, v, 4, 8);
        v += __shfl_xor_sync(0xffffffffu, v, 2, 8);
        v += __shfl_xor_sync(0xffffffffu, v, 1, 8);
        if (j == 0) gsumv[h] = v;
    }
    __syncthreads();
    if (tid < 16) rinv[tid] = 1.f / gsumv[tid];
    __syncthreads();

    float a0 = 0.f, a1 = 0.f, a2 = 0.f, a3 = 0.f;
#pragma unroll
    for (int h = 0; h < NH; h++) {
        const float iv = rinv[h];
        a0 = fmaf(sc[h][0], iv, a0);
        a1 = fmaf(sc[h][1], iv, a1);
        a2 = fmaf(sc[h][2], iv, a2);
        a3 = fmaf(sc[h][3], iv, a3);
    }
    const float w = 1.f / (float)NH;
    float4 o = make_float4(a0 * w, a1 * w, a2 * w, a3 * w);
    ((float4*)out)[((size_t)(b * SEQ + q)) * 256 + tid] = o;
}

// ---------------------------------------------------------------------------
extern "C" void kernel_launch(void* const* d_in, const int* in_sizes, int n_in,
                              void* d_out, int out_size)
{
    const float* x    = (const float*)d_in[0];
    const int*   mask = (const int*)d_in[1];
    const float* Wq   = (const float*)d_in[2];
    const float* bq   = (const float*)d_in[3];
    const float* Wk   = (const float*)d_in[4];
    const float* bk   = (const float*)d_in[5];
    const float* gq   = (const float*)d_in[6];
    const float* bqn  = (const float*)d_in[7];
    const float* gk   = (const float*)d_in[8];
    const float* bkn  = (const float*)d_in[9];
    float* out = (float*)d_out;

    split_x <<<4096, 256>>>(x);
    split_wt<<<dim3(16, 16, 2), 256>>>(Wq, Wk);
    mask_or <<<dim3(32, 32, 4), 256>>>(mask);
    proj_mma<<<296, 256>>>(bq, bk);
    ln_relu <<<dim3(4096, 2), 256>>>(gq, bqn, gk, bkn);
    score_mma<<<dim3(8, 8, 64), 256>>>();
    softmax_mean<<<dim3(1024, 4), 256>>>(out);
}

// round 17
// speedup vs baseline: 1.0769x; 1.0769x over previous
#include <cuda_runtime.h>
#include <cuda_fp16.h>
#include <math.h>
#include <stdint.h>

// Problem constants
#define EMB   1024
#define NROWS 4096          // B * S
#define NH    16
#define HD    64
#define SEQ   1024
#define NB    4
#define NEGV  (-1e9f)

// Scratch (device globals: allocation-free, graph-capturable)
__device__ float          g_P [2][(size_t)NROWS * EMB];      // proj outputs (pre-LN)
__device__ __half         g_x  [(size_t)NROWS * EMB];        // x, fp16
__device__ __half         g_w  [2][(size_t)EMB * EMB];       // W^T fp16
__device__ __half         g_q  [(size_t)NROWS * EMB];        // Q fp16
__device__ __half         g_k  [(size_t)NROWS * EMB];        // K fp16
__device__ __half         g_S  [(size_t)NB * NH * SEQ * SEQ]; // scores fp16, 128 MB
__device__ unsigned char  g_M  [(size_t)NB * SEQ * SEQ];     // symmetric mask, 4 MB

// ===========================================================================
// helpers
// ===========================================================================
__device__ __forceinline__ uint32_t smem_u32(const void* p) {
    uint32_t a;
    asm("{ .reg .u64 t; cvta.to.shared.u64 t, %1; cvt.u32.u64 %0, t; }"
        : "=r"(a) : "l"(p));
    return a;
}

#define CP16(s, g) \
    asm volatile("cp.async.cg.shared.global [%0], [%1], 16;" :: "r"(s), "l"(g))
#define CP_COMMIT() asm volatile("cp.async.commit_group;" ::: "memory")
#define CP_WAIT(n)  asm volatile("cp.async.wait_group %0;" :: "n"(n) : "memory")

__device__ __forceinline__ void ldsm4(uint32_t addr, uint32_t r[4]) {
    asm volatile("ldmatrix.sync.aligned.m8n8.x4.shared.b16 {%0,%1,%2,%3}, [%4];"
        : "=r"(r[0]), "=r"(r[1]), "=r"(r[2]), "=r"(r[3]) : "r"(addr));
}
__device__ __forceinline__ void mma16816(float c[4], const uint32_t a[4],
                                         uint32_t b0, uint32_t b1) {
    asm volatile(
        "mma.sync.aligned.m16n8k16.row.col.f32.f16.f16.f32 "
        "{%0,%1,%2,%3}, {%4,%5,%6,%7}, {%8,%9}, {%0,%1,%2,%3};"
        : "+f"(c[0]), "+f"(c[1]), "+f"(c[2]), "+f"(c[3])
        : "r"(a[0]), "r"(a[1]), "r"(a[2]), "r"(a[3]), "r"(b0), "r"(b1));
}

// ===========================================================================
// core 128x128 GEMM tile, C = A @ B^T, fp16 operands, fp32 accumulate.
// (unchanged from R15)
// ===========================================================================
template <int KCHUNKS>
__device__ __forceinline__ void gemm_tile(
    const __half* __restrict__ A,
    const __half* __restrict__ B,
    float acc[2][8][4])
{
    __shared__ __half sm[2][2][128 * 40];
    const uint32_t sbase = smem_u32(&sm[0][0][0]);
    const int t = threadIdx.x, lane = t & 31, wid = t >> 5;
    const int wm = wid & 3, wn = wid >> 2;

    const int rA0 = t >> 2, cc = t & 3;
    const int rA1 = rA0 + 64;
    const uint32_t so0 = (uint32_t)(rA0 * 80 + cc * 16);
    const uint32_t so1 = (uint32_t)(rA1 * 80 + cc * 16);

    uint32_t aoff[2], boff[4];
#pragma unroll
    for (int mf = 0; mf < 2; mf++)
        aoff[mf] = (uint32_t)((wm * 32 + mf * 16 + (lane & 15)) * 80 + (lane >> 4) * 16);
#pragma unroll
    for (int g = 0; g < 4; g++)
        boff[g] = (uint32_t)((wn * 64 + g * 16 + (lane & 15)) * 80 + (lane >> 4) * 16);

    auto issue = [&](int buf, int c) {
        const uint32_t sA = sbase + (uint32_t)buf * 20480u;
        const uint32_t sB = sA + 10240u;
        const __half* ga = A + c * 32;
        const __half* gb = B + c * 32;
        CP16(sA + so0, ga + (size_t)rA0 * EMB + cc * 8);
        CP16(sA + so1, ga + (size_t)rA1 * EMB + cc * 8);
        CP16(sB + so0, gb + (size_t)rA0 * EMB + cc * 8);
        CP16(sB + so1, gb + (size_t)rA1 * EMB + cc * 8);
        CP_COMMIT();
    };

    issue(0, 0);
    for (int c = 0; c < KCHUNKS; c++) {
        const int buf = c & 1;
        if (c + 1 < KCHUNKS) { issue(buf ^ 1, c + 1); CP_WAIT(1); }
        else                 { CP_WAIT(0); }
        __syncthreads();
        const uint32_t sA = sbase + (uint32_t)buf * 20480u;
        const uint32_t sB = sA + 10240u;
#pragma unroll
        for (int ks = 0; ks < 2; ks++) {
            uint32_t a0[4], a1[4], b0[4], b1[4], b2[4], b3[4];
            ldsm4(sA + aoff[0] + ks * 32, a0);
            ldsm4(sA + aoff[1] + ks * 32, a1);
            ldsm4(sB + boff[0] + ks * 32, b0);
            ldsm4(sB + boff[1] + ks * 32, b1);
            ldsm4(sB + boff[2] + ks * 32, b2);
            ldsm4(sB + boff[3] + ks * 32, b3);
            mma16816(acc[0][0], a0, b0[0], b0[2]);
            mma16816(acc[0][1], a0, b0[1], b0[3]);
            mma16816(acc[1][0], a1, b0[0], b0[2]);
            mma16816(acc[1][1], a1, b0[1], b0[3]);
            mma16816(acc[0][2], a0, b1[0], b1[2]);
            mma16816(acc[0][3], a0, b1[1], b1[3]);
            mma16816(acc[1][2], a1, b1[0], b1[2]);
            mma16816(acc[1][3], a1, b1[1], b1[3]);
            mma16816(acc[0][4], a0, b2[0], b2[2]);
            mma16816(acc[0][5], a0, b2[1], b2[3]);
            mma16816(acc[1][4], a1, b2[0], b2[2]);
            mma16816(acc[1][5], a1, b2[1], b2[3]);
            mma16816(acc[0][6], a0, b3[0], b3[2]);
            mma16816(acc[0][7], a0, b3[1], b3[3]);
            mma16816(acc[1][6], a1, b3[0], b3[2]);
            mma16816(acc[1][7], a1, b3[1], b3[3]);
        }
        __syncthreads();
    }
}

// ===========================================================================
// Kernel A: x -> fp16
// ===========================================================================
__global__ __launch_bounds__(256) void split_x(const float* __restrict__ x)
{
    size_t i = ((size_t)blockIdx.x * 256 + threadIdx.x) * 4;
    float4 v = *(const float4*)(x + i);
    __half2 p0 = __floats2half2_rn(v.x, v.y);
    __half2 p1 = __floats2half2_rn(v.z, v.w);
    *(__half2*)(g_x + i)     = p0;
    *(__half2*)(g_x + i + 2) = p1;
}

// ===========================================================================
// Kernel B: transpose W -> W^T fp16.  grid (16,16,2), 64x64 tiles, 256 thr
// ===========================================================================
__global__ __launch_bounds__(256) void split_wt(
    const float* __restrict__ Wq, const float* __restrict__ Wk)
{
    __shared__ float t[64][65];
    const int which = blockIdx.z;
    const float* __restrict__ W = which ? Wk : Wq;
    const int n0 = blockIdx.x * 64, k0 = blockIdx.y * 64;
    const int c = threadIdx.x & 63, rb = threadIdx.x >> 6;

#pragma unroll
    for (int rr = 0; rr < 16; rr++) {
        int r = rb * 16 + rr;
        t[r][c] = W[(size_t)(k0 + r) * EMB + n0 + c];
    }
    __syncthreads();
#pragma unroll
    for (int rr = 0; rr < 16; rr++) {
        int r = rb * 16 + rr;
        float v = t[c][r];
        g_w[which][(size_t)(n0 + r) * EMB + (size_t)(k0 + c)] = __float2half_rn(v);
    }
}

// ===========================================================================
// Kernel B2: symmetric mask.  M[b][q][k] = mask[b][q][k] | mask[b][k][q]
// ===========================================================================
__global__ __launch_bounds__(256) void mask_or(const int* __restrict__ mask)
{
    __shared__ int tB[32][33];
    const int b  = blockIdx.z;
    const int q0 = blockIdx.y * 32;
    const int k0 = blockIdx.x * 32;
    const int r  = threadIdx.x >> 3;
    const int c4 = (threadIdx.x & 7) * 4;

    int4 tb = *(const int4*)&mask[((size_t)(b * SEQ + k0 + r)) * SEQ + q0 + c4];
    tB[r][c4 + 0] = tb.x; tB[r][c4 + 1] = tb.y;
    tB[r][c4 + 2] = tb.z; tB[r][c4 + 3] = tb.w;
    __syncthreads();

    int4 a = *(const int4*)&mask[((size_t)(b * SEQ + q0 + r)) * SEQ + k0 + c4];
    uchar4 o;
    o.x = (a.x | tB[c4 + 0][r]) ? 1 : 0;
    o.y = (a.y | tB[c4 + 1][r]) ? 1 : 0;
    o.z = (a.z | tB[c4 + 2][r]) ? 1 : 0;
    o.w = (a.w | tB[c4 + 3][r]) ? 1 : 0;
    *(uchar4*)&g_M[((size_t)(b * SEQ + q0 + r)) * SEQ + k0 + c4] = o;
}

// ===========================================================================
// Kernel C: projection GEMM, P = x @ W + b.  grid (8 N, 32 M, 2 which), 256 thr
// (R15 launch shape — persistent variant reverted)
// ===========================================================================
__global__ __launch_bounds__(256, 2) void proj_mma(
    const float* __restrict__ bq, const float* __restrict__ bk)
{
    const int n0 = blockIdx.x * 128, m0 = blockIdx.y * 128, which = blockIdx.z;
    const __half* A = g_x + (size_t)m0 * EMB;
    const __half* B = g_w[which] + (size_t)n0 * EMB;

    float acc[2][8][4] = {};
    gemm_tile<32>(A, B, acc);

    const float* __restrict__ bias = which ? bk : bq;
    float* __restrict__ P = g_P[which];
    const int lane = threadIdx.x & 31, wid = threadIdx.x >> 5;
    const int wm = wid & 3, wn = wid >> 2;

#pragma unroll
    for (int mf = 0; mf < 2; mf++) {
#pragma unroll
        for (int j = 0; j < 8; j++) {
            int row = m0 + wm * 32 + mf * 16 + (lane >> 2);
            int col = n0 + wn * 64 + j * 8 + (lane & 3) * 2;
            float b0 = bias[col], b1 = bias[col + 1];
            float2 o0 = make_float2(acc[mf][j][0] + b0, acc[mf][j][1] + b1);
            float2 o1 = make_float2(acc[mf][j][2] + b0, acc[mf][j][3] + b1);
            *(float2*)&P[(size_t)row * EMB + col]       = o0;
            *(float2*)&P[(size_t)(row + 8) * EMB + col] = o1;
        }
    }
}

// ---------------------------------------------------------------------------
// fused pair block reduction (sum), 256 threads, 2 barriers
// ---------------------------------------------------------------------------
__device__ __forceinline__ float2 block_reduce_pair(float a, float b)
{
    __shared__ float red[8][2];
    const int lane = threadIdx.x & 31;
    const int w    = threadIdx.x >> 5;
#pragma unroll
    for (int o = 16; o; o >>= 1) {
        a += __shfl_xor_sync(0xffffffffu, a, o);
        b += __shfl_xor_sync(0xffffffffu, b, o);
    }
    if (lane == 0) { red[w][0] = a; red[w][1] = b; }
    __syncthreads();
    if (w == 0) {
        float x = (lane < 8) ? red[lane][0] : 0.f;
        float y = (lane < 8) ? red[lane][1] : 0.f;
#pragma unroll
        for (int o = 4; o; o >>= 1) {
            x += __shfl_xor_sync(0xffffffffu, x, o);
            y += __shfl_xor_sync(0xffffffffu, y, o);
        }
        if (lane == 0) { red[0][0] = x; red[0][1] = y; }
    }
    __syncthreads();
    return make_float2(red[0][0], red[0][1]);
}

// ---------------------------------------------------------------------------
// Kernel D: LayerNorm + ReLU -> fp16.  grid (4096, 2), 256 threads
// ---------------------------------------------------------------------------
__global__ __launch_bounds__(256) void ln_relu(
    const float* __restrict__ gq, const float* __restrict__ bqn,
    const float* __restrict__ gk, const float* __restrict__ bkn)
{
    const int row   = blockIdx.x;
    const int which = blockIdx.y;
    const int tid   = threadIdx.x;
    const float* __restrict__ gamma = which ? gk : gq;
    const float* __restrict__ beta  = which ? bkn : bqn;

    float4 v = ((const float4*)g_P[which])[(size_t)row * 256 + tid];
    float s  = v.x + v.y + v.z + v.w;
    float s2 = v.x * v.x + v.y * v.y + v.z * v.z + v.w * v.w;

    float2 SS = block_reduce_pair(s, s2);

    const float mu  = SS.x * (1.f / EMB);
    const float var = SS.y * (1.f / EMB) - mu * mu;
    const float rs  = rsqrtf(var + 1e-5f);

    const int c = tid * 4;
    float f[4];
    f[0] = fmaxf((v.x - mu) * rs * gamma[c + 0] + beta[c + 0], 0.f);
    f[1] = fmaxf((v.y - mu) * rs * gamma[c + 1] + beta[c + 1], 0.f);
    f[2] = fmaxf((v.z - mu) * rs * gamma[c + 2] + beta[c + 2], 0.f);
    f[3] = fmaxf((v.w - mu) * rs * gamma[c + 3] + beta[c + 3], 0.f);

    __half* dst = which ? g_k : g_q;
    size_t base = (size_t)row * EMB + c;
    *(__half2*)(dst + base)     = __floats2half2_rn(f[0], f[1]);
    *(__half2*)(dst + base + 2) = __floats2half2_rn(f[2], f[3]);
}

// ===========================================================================
// Kernel E: score GEMM. S[b,h][q][k] = (Q_h . K_h)/8, stored fp16.
// grid (8 kt, 8 qt, 64 bh), 256 threads
// ===========================================================================
__global__ __launch_bounds__(256, 2) void score_mma()
{
    const int kt = blockIdx.x, qt = blockIdx.y, bh = blockIdx.z;
    const int b = bh >> 4, h = bh & 15;

    const __half* A = g_q + (size_t)(b * SEQ + qt * 128) * EMB + h * HD;
    const __half* B = g_k + (size_t)(b * SEQ + kt * 128) * EMB + h * HD;

    float acc[2][8][4] = {};
    gemm_tile<2>(A, B, acc);

    const int lane = threadIdx.x & 31, wid = threadIdx.x >> 5;
    const int wm = wid & 3, wn = wid >> 2;

#pragma unroll
    for (int mf = 0; mf < 2; mf++) {
#pragma unroll
        for (int j = 0; j < 8; j++) {
            int q   = qt * 128 + wm * 32 + mf * 16 + (lane >> 2);
            int col = kt * 128 + wn * 64 + j * 8 + (lane & 3) * 2;
            __half2 o0 = __floats2half2_rn(acc[mf][j][0] * 0.125f, acc[mf][j][1] * 0.125f);
            __half2 o1 = __floats2half2_rn(acc[mf][j][2] * 0.125f, acc[mf][j][3] * 0.125f);
            __half* S = g_S + ((size_t)bh * SEQ) * SEQ;
            *(__half2*)&S[(size_t)q * SEQ + col]       = o0;
            *(__half2*)&S[(size_t)(q + 8) * SEQ + col] = o1;
        }
    }
}

// ---------------------------------------------------------------------------
// Kernel F: no-max softmax + mean over heads, MLP-preserving schedule,
// fp16 score loads (uint2 = 4 halves per head per thread).
// ---------------------------------------------------------------------------
__global__ __launch_bounds__(256, 2) void softmax_mean(float* __restrict__ out)
{
    __shared__ float sred[16][8];
    __shared__ float gsumv[16];
    __shared__ float rinv[16];

    const int q    = blockIdx.x;
    const int b    = blockIdx.y;
    const int tid  = threadIdx.x;
    const int lane = tid & 31;
    const int wid  = tid >> 5;

    uchar4 mb = ((const uchar4*)(g_M + ((size_t)(b * SEQ + q)) * SEQ))[tid];
    const bool m0 = mb.x, m1 = mb.y, m2 = mb.z, m3 = mb.w;

    // phase 1: batched fp16 loads, cheap convert + mask-select body
    float sc[16][4];
#pragma unroll
    for (int h = 0; h < NH; h++) {
        const uint2* Sp = (const uint2*)(g_S + (((size_t)(b * NH + h) * SEQ + q) << 10));
        uint2 raw = Sp[tid];
        float2 f01 = __half22float2(*(__half2*)&raw.x);
        float2 f23 = __half22float2(*(__half2*)&raw.y);
        sc[h][0] = m0 ? NEGV : f01.x;
        sc[h][1] = m1 ? NEGV : f01.y;
        sc[h][2] = m2 ? NEGV : f23.x;
        sc[h][3] = m3 ? NEGV : f23.y;
    }

    // phase 2: exp + per-thread partial sums
    float tval[16];
#pragma unroll
    for (int h = 0; h < NH; h++) {
        sc[h][0] = __expf(sc[h][0]);
        sc[h][1] = __expf(sc[h][1]);
        sc[h][2] = __expf(sc[h][2]);
        sc[h][3] = __expf(sc[h][3]);
        tval[h] = (sc[h][0] + sc[h][1]) + (sc[h][2] + sc[h][3]);
    }

    // single batched sum reduction for all 16 heads
#pragma unroll
    for (int h = 0; h < NH; h++) {
        float v = tval[h];
#pragma unroll
        for (int o = 16; o; o >>= 1) v += __shfl_xor_sync(0xffffffffu, v, o);
        if (lane == h) sred[h][wid] = v;
    }
    __syncthreads();
    if (tid < 128) {
        const int h = tid >> 3, j = tid & 7;
        float v = sred[h][j];
        v += __shfl_xor_sync(0xffffffffu, v, 4, 8);
        v += __shfl_xor_sync(0xffffffffu, v, 2, 8);
        v += __shfl_xor_sync(0xffffffffu, v, 1, 8);
        if (j == 0) gsumv[h] = v;
    }
    __syncthreads();
    if (tid < 16) rinv[tid] = 1.f / gsumv[tid];
    __syncthreads();

    float a0 = 0.f, a1 = 0.f, a2 = 0.f, a3 = 0.f;
#pragma unroll
    for (int h = 0; h < NH; h++) {
        const float iv = rinv[h];
        a0 = fmaf(sc[h][0], iv, a0);
        a1 = fmaf(sc[h][1], iv, a1);
        a2 = fmaf(sc[h][2], iv, a2);
        a3 = fmaf(sc[h][3], iv, a3);
    }
    const float w = 1.f / (float)NH;
    float4 o = make_float4(a0 * w, a1 * w, a2 * w, a3 * w);
    ((float4*)out)[((size_t)(b * SEQ + q)) * 256 + tid] = o;
}

// ---------------------------------------------------------------------------
extern "C" void kernel_launch(void* const* d_in, const int* in_sizes, int n_in,
                              void* d_out, int out_size)
{
    const float* x    = (const float*)d_in[0];
    const int*   mask = (const int*)d_in[1];
    const float* Wq   = (const float*)d_in[2];
    const float* bq   = (const float*)d_in[3];
    const float* Wk   = (const float*)d_in[4];
    const float* bk   = (const float*)d_in[5];
    const float* gq   = (const float*)d_in[6];
    const float* bqn  = (const float*)d_in[7];
    const float* gk   = (const float*)d_in[8];
    const float* bkn  = (const float*)d_in[9];
    float* out = (float*)d_out;

    split_x <<<4096, 256>>>(x);
    split_wt<<<dim3(16, 16, 2), 256>>>(Wq, Wk);
    mask_or <<<dim3(32, 32, 4), 256>>>(mask);
    proj_mma<<<dim3(8, 32, 2), 256>>>(bq, bk);
    ln_relu <<<dim3(4096, 2), 256>>>(gq, bqn, gk, bkn);
    score_mma<<<dim3(8, 8, 64), 256>>>();
    softmax_mean<<<dim3(1024, 4), 256>>>(out);
}